// round 7
// baseline (speedup 1.0000x reference)
#include <cuda_runtime.h>
#include <cstddef>

// Problem constants
#define BATCH 256
#define LSEQ  128
#define DD    6
#define FF    200
#define FA_   39
#define FB_   10
#define RR    2
#define MROWS (BATCH*LSEQ)          // 32768
#define MSLOT (MROWS*DD)            // 196608

// ---------------- scratch (device globals; no allocations allowed) ----------
__device__ float g_cur   [(size_t)MROWS*FF];
__device__ float g_ctxpre[(size_t)MROWS*FF];
__device__ float g_ctx   [(size_t)MROWS*FF];
__device__ float g_s     [MROWS];
__device__ float g_gi    [(size_t)MROWS*3*FF];
__device__ float g_gh    [(size_t)MROWS*3*FF];
__device__ float g_nbr   [(size_t)MSLOT*FF];
__device__ float g_acat  [(size_t)MSLOT*(FA_+FB_)];

// =================== tf32 tensor-core SGEMM v2 ==============================
//   C[M,N] = act(A[M,K] @ W[N,K]^T + bias[N]*rowscale[M])
//   ACT: 0=none, 1=leaky_relu(0.01), 2=elu
// BM=128, BN=64, BK=16; 256 threads = 8 warps (4 M x 2 N), warp tile 32x32.
// Smem layout: word for k stored at chunk (k&3)^(row&3), word-in-chunk (k>>2).
// -> each thread's A/B fragment for a whole BK=16 tile is ONE 16B LDS.128.
#define TBM 128
#define TBN 64
#define TBK 16

__device__ __forceinline__ unsigned f2tf32(float x) {
    unsigned r;
    asm("cvt.rna.tf32.f32 %0, %1;" : "=r"(r) : "f"(x));
    return r;
}

__device__ __forceinline__ void mma_tf32(float* c,
                                         unsigned a0, unsigned a1, unsigned a2, unsigned a3,
                                         unsigned b0, unsigned b1) {
    asm volatile(
        "mma.sync.aligned.m16n8k8.row.col.f32.tf32.tf32.f32 "
        "{%0,%1,%2,%3}, {%4,%5,%6,%7}, {%8,%9}, {%0,%1,%2,%3};"
        : "+f"(c[0]), "+f"(c[1]), "+f"(c[2]), "+f"(c[3])
        : "r"(a0), "r"(a1), "r"(a2), "r"(a3), "r"(b0), "r"(b1));
}

// swizzled word index within a 16-word row for element k of row m
__device__ __forceinline__ int swidx(int k, int m) {
    return (((k & 3) ^ (m & 3)) << 2) + (k >> 2);
}

template<int ACT, int VEC>
__global__ void __launch_bounds__(256)
sgemm_tc(const float* __restrict__ A, const float* __restrict__ W,
         const float* __restrict__ bias, const float* __restrict__ rowscale,
         float* __restrict__ C, int M, int N, int K)
{
    __shared__ __align__(16) unsigned As[2][TBM][TBK];
    __shared__ __align__(16) unsigned Bs[2][TBN][TBK];

    const int tid   = threadIdx.x;
    const int lane  = tid & 31;
    const int warp  = tid >> 5;
    const int warpM = warp >> 1;        // 0..3
    const int warpN = warp & 1;         // 0..1
    const int mBase = blockIdx.y * TBM;
    const int nBase = blockIdx.x * TBN;
    const int nk    = (K + TBK - 1) / TBK;

    const int r0 = lane >> 2;
    const int c0 = lane & 3;
    // swizzled chunk column: constant per thread (row bases are ≡0 mod 8)
    const int swc = ((c0 ^ (r0 & 3)) << 2);

    float acc[2][4][4];
    #pragma unroll
    for (int mt = 0; mt < 2; mt++)
        #pragma unroll
        for (int nt = 0; nt < 4; nt++)
            #pragma unroll
            for (int i = 0; i < 4; i++) acc[mt][nt][i] = 0.f;

    // staging registers
    float4 arv[2]; float4 brv;          // vector path
    float  ars[8]; float  brs[4];       // scalar path

#define LDG_TILE(KT)                                                           \
    {                                                                          \
        int kbase = (KT) * TBK;                                                \
        if (VEC) {                                                             \
            _Pragma("unroll")                                                  \
            for (int it = 0; it < 2; it++) {                                   \
                int e = tid + it * 256;                                        \
                int m = e >> 2, kq = e & 3;                                    \
                int gk = kbase + kq * 4;                                       \
                arv[it] = (gk < K)                                             \
                    ? *(const float4*)&A[(size_t)(mBase + m) * K + gk]         \
                    : make_float4(0.f, 0.f, 0.f, 0.f);                         \
            }                                                                  \
            {                                                                  \
                int n = tid >> 2, kq = tid & 3;                                \
                int gn = nBase + n, gk = kbase + kq * 4;                       \
                brv = (gn < N && gk < K)                                       \
                    ? *(const float4*)&W[(size_t)gn * K + gk]                  \
                    : make_float4(0.f, 0.f, 0.f, 0.f);                         \
            }                                                                  \
        } else {                                                               \
            _Pragma("unroll")                                                  \
            for (int i = 0; i < 8; i++) {                                      \
                int e = tid + i * 256;                                         \
                int m = e >> 4, k = e & 15;                                    \
                int gk = kbase + k;                                            \
                ars[i] = (gk < K) ? A[(size_t)(mBase + m) * K + gk] : 0.f;     \
            }                                                                  \
            _Pragma("unroll")                                                  \
            for (int i = 0; i < 4; i++) {                                      \
                int e = tid + i * 256;                                         \
                int n = e >> 4, k = e & 15;                                    \
                int gn = nBase + n, gk = kbase + k;                            \
                brs[i] = (gn < N && gk < K) ? W[(size_t)gn * K + gk] : 0.f;    \
            }                                                                  \
        }                                                                      \
    }

#define STS_TILE(BUF)                                                          \
    {                                                                          \
        if (VEC) {                                                             \
            _Pragma("unroll")                                                  \
            for (int it = 0; it < 2; it++) {                                   \
                int e = tid + it * 256;                                        \
                int m = e >> 2, kq = e & 3;                                    \
                float v[4] = {arv[it].x, arv[it].y, arv[it].z, arv[it].w};     \
                _Pragma("unroll")                                              \
                for (int j = 0; j < 4; j++)                                    \
                    As[BUF][m][swidx(kq * 4 + j, m)] = f2tf32(v[j]);           \
            }                                                                  \
            {                                                                  \
                int n = tid >> 2, kq = tid & 3;                                \
                float v[4] = {brv.x, brv.y, brv.z, brv.w};                     \
                _Pragma("unroll")                                              \
                for (int j = 0; j < 4; j++)                                    \
                    Bs[BUF][n][swidx(kq * 4 + j, n)] = f2tf32(v[j]);           \
            }                                                                  \
        } else {                                                               \
            _Pragma("unroll")                                                  \
            for (int i = 0; i < 8; i++) {                                      \
                int e = tid + i * 256;                                         \
                int m = e >> 4, k = e & 15;                                    \
                As[BUF][m][swidx(k, m)] = f2tf32(ars[i]);                      \
            }                                                                  \
            _Pragma("unroll")                                                  \
            for (int i = 0; i < 4; i++) {                                      \
                int e = tid + i * 256;                                         \
                int n = e >> 4, k = e & 15;                                    \
                Bs[BUF][n][swidx(k, n)] = f2tf32(brs[i]);                      \
            }                                                                  \
        }                                                                      \
    }

    LDG_TILE(0);
    STS_TILE(0);
    __syncthreads();

    const int rowA = warpM * 32 + r0;   // + mt*16 (+8)
    const int rowB = warpN * 32 + r0;   // + nt*8

    for (int kt = 0; kt < nk; kt++) {
        int buf = kt & 1;
        if (kt + 1 < nk) LDG_TILE(kt + 1);

        // one LDS.128 per fragment row covers BOTH kk steps of this k-tile
        uint4 av[2][2], bv[4];
        #pragma unroll
        for (int mt = 0; mt < 2; mt++) {
            av[mt][0] = *(const uint4*)&As[buf][rowA + mt * 16    ][swc];
            av[mt][1] = *(const uint4*)&As[buf][rowA + mt * 16 + 8][swc];
        }
        #pragma unroll
        for (int nt = 0; nt < 4; nt++)
            bv[nt] = *(const uint4*)&Bs[buf][rowB + nt * 8][swc];

        #pragma unroll
        for (int mt = 0; mt < 2; mt++)
            #pragma unroll
            for (int nt = 0; nt < 4; nt++) {
                // kk = 0: k = c0, c0+4  -> components .x, .y
                mma_tf32(acc[mt][nt],
                         av[mt][0].x, av[mt][1].x, av[mt][0].y, av[mt][1].y,
                         bv[nt].x, bv[nt].y);
                // kk = 1: k = c0+8, c0+12 -> components .z, .w
                mma_tf32(acc[mt][nt],
                         av[mt][0].z, av[mt][1].z, av[mt][0].w, av[mt][1].w,
                         bv[nt].z, bv[nt].w);
            }

        if (kt + 1 < nk) {
            STS_TILE((kt + 1) & 1);
            __syncthreads();
        }
    }

    // -------- epilogue --------
    #pragma unroll
    for (int mt = 0; mt < 2; mt++) {
        int row0 = mBase + warpM * 32 + mt * 16 + r0;
        float s0 = rowscale ? rowscale[row0]     : 1.f;
        float s1 = rowscale ? rowscale[row0 + 8] : 1.f;
        #pragma unroll
        for (int nt = 0; nt < 4; nt++) {
            int col0 = nBase + warpN * 32 + nt * 8 + c0 * 2;
            #pragma unroll
            for (int j = 0; j < 2; j++) {
                int col = col0 + j;
                if (col < N) {
                    float bv2 = bias[col];
                    float v0 = acc[mt][nt][j]     + bv2 * s0;
                    float v1 = acc[mt][nt][j + 2] + bv2 * s1;
                    if (ACT == 1) {
                        v0 = (v0 > 0.f) ? v0 : 0.01f * v0;
                        v1 = (v1 > 0.f) ? v1 : 0.01f * v1;
                    } else if (ACT == 2) {
                        v0 = (v0 > 0.f) ? v0 : expm1f(v0);
                        v1 = (v1 > 0.f) ? v1 : expm1f(v1);
                    }
                    C[(size_t)row0 * N + col]       = v0;
                    C[(size_t)(row0 + 8) * N + col] = v1;
                }
            }
        }
    }
#undef LDG_TILE
#undef STS_TILE
}

// ---------------- gather concat(atom_nbr, bond_nbr) into [MSLOT, 49] --------
__global__ void gather_acat_kernel(const float* __restrict__ atom_list,
                                   const float* __restrict__ bond_list,
                                   const int*   __restrict__ adeg,
                                   const int*   __restrict__ bdeg,
                                   float* __restrict__ acat)
{
    const int KC = FA_ + FB_; // 49
    int e = blockIdx.x * blockDim.x + threadIdx.x;
    if (e >= MSLOT * KC) return;
    int slot = e / KC;
    int k    = e - slot * KC;
    int b    = slot / (LSEQ * DD);
    float v;
    if (k < FA_) {
        int a = adeg[slot];
        v = atom_list[((size_t)b * LSEQ + a) * FA_ + k];
    } else {
        int bb = bdeg[slot];
        v = bond_list[((size_t)b * LSEQ + bb) * FB_ + (k - FA_)];
    }
    acat[e] = v;
}

// ---------------- attention: warp per row ----------------------------------
__global__ void __launch_bounds__(256)
attention_kernel(const float* __restrict__ cur,      // [MROWS,F]
                 const float* __restrict__ nbrfeat,  // [MSLOT,F] (round 0 only)
                 const int*   __restrict__ adeg,     // [MROWS,D]
                 const float* __restrict__ alignW,   // [2F] (this round)
                 const float* __restrict__ alignB,   // [1]
                 float* __restrict__ ctxpre,
                 float* __restrict__ srow,
                 int first)
{
    int gw   = (blockIdx.x * blockDim.x + threadIdx.x) >> 5;
    int lane = threadIdx.x & 31;
    if (gw >= MROWS) return;
    const int r = gw;
    const int b = r >> 7;
    const float ab = alignB[0];

    float cv[7], a0[7], a1[7];
    #pragma unroll
    for (int i = 0; i < 7; i++) {
        int idx = lane + 32 * i;
        bool ok = idx < FF;
        cv[i] = ok ? cur[(size_t)r * FF + idx] : 0.f;
        a0[i] = ok ? alignW[idx]       : 0.f;
        a1[i] = ok ? alignW[FF + idx]  : 0.f;
    }
    float qd = 0.f;
    #pragma unroll
    for (int i = 0; i < 7; i++) qd += cv[i] * a0[i];
    #pragma unroll
    for (int o = 16; o > 0; o >>= 1) qd += __shfl_xor_sync(0xffffffffu, qd, o);

    float nv[DD][7];
    float score[DD];
    int   nai[DD];

    #pragma unroll
    for (int d = 0; d < DD; d++) {
        int na = adeg[r * DD + d];
        nai[d] = na;
        const float* np = first ? (nbrfeat + ((size_t)r * DD + d) * FF)
                                : (cur + ((size_t)(b * LSEQ + na)) * FF);
        float nd = 0.f;
        #pragma unroll
        for (int i = 0; i < 7; i++) {
            int idx = lane + 32 * i;
            float v = (idx < FF) ? np[idx] : 0.f;
            nv[d][i] = v;
            nd += v * a1[i];
        }
        #pragma unroll
        for (int o = 16; o > 0; o >>= 1) nd += __shfl_xor_sync(0xffffffffu, nd, o);
        float sc = qd + nd + ab;
        sc = (sc > 0.f) ? sc : 0.01f * sc;   // leaky_relu
        if (na == LSEQ - 1) sc = sc - 9e8f;  // softmax mask (pad)
        score[d] = sc;
    }

    float mx = score[0];
    #pragma unroll
    for (int d = 1; d < DD; d++) mx = fmaxf(mx, score[d]);
    float e[DD], den = 0.f;
    #pragma unroll
    for (int d = 0; d < DD; d++) { e[d] = expf(score[d] - mx); den += e[d]; }
    float inv = 1.f / den;
    float s = 0.f;
    #pragma unroll
    for (int d = 0; d < DD; d++) {
        float a = e[d] * inv;
        if (nai[d] == LSEQ - 1) a = 0.f;     // attend mask
        e[d] = a;
        s += a;
    }

    #pragma unroll
    for (int i = 0; i < 7; i++) {
        int idx = lane + 32 * i;
        if (idx < FF) {
            float v = 0.f;
            #pragma unroll
            for (int d = 0; d < DD; d++) v += e[d] * nv[d][i];
            ctxpre[(size_t)r * FF + idx] = v;
        }
    }
    if (lane == 0) srow[r] = s;
}

// ---------------- GRU pointwise ---------------------------------------------
__global__ void gru_kernel(const float* __restrict__ gi, const float* __restrict__ gh,
                           const float* __restrict__ cur, float* __restrict__ out)
{
    int idx = blockIdx.x * blockDim.x + threadIdx.x;
    if (idx >= MROWS * FF) return;
    int r = idx / FF;
    int j = idx - r * FF;
    size_t base = (size_t)r * 3 * FF + j;
    float ir = gi[base], iz = gi[base + FF], in_ = gi[base + 2 * FF];
    float hr = gh[base], hz = gh[base + FF], hn  = gh[base + 2 * FF];
    float rr = 1.f / (1.f + expf(-(ir + hr)));
    float z  = 1.f / (1.f + expf(-(iz + hz)));
    float n  = tanhf(in_ + rr * hn);
    float c  = cur[idx];
    float h  = (1.f - z) * n + z * c;
    out[idx] = (h > 0.f) ? h : 0.f;          // relu
}

// ---------------- launch ------------------------------------------------------
static inline int ceil_div(int a, int b) { return (a + b - 1) / b; }

extern "C" void kernel_launch(void* const* d_in, const int* in_sizes, int n_in,
                              void* d_out, int out_size)
{
    const float* atom_list = (const float*)d_in[0];
    const float* bond_list = (const float*)d_in[1];
    const int*   adeg      = (const int*)  d_in[2];
    const int*   bdeg      = (const int*)  d_in[3];
    const float* atom_W    = (const float*)d_in[4];
    const float* atom_b    = (const float*)d_in[5];
    const float* nbr_W     = (const float*)d_in[6];
    const float* nbr_b     = (const float*)d_in[7];
    const float* align_W   = (const float*)d_in[8];
    const float* align_b   = (const float*)d_in[9];
    const float* attend_W  = (const float*)d_in[10];
    const float* attend_b  = (const float*)d_in[11];
    const float* gWih      = (const float*)d_in[12];
    const float* gWhh      = (const float*)d_in[13];
    const float* gbih      = (const float*)d_in[14];
    const float* gbhh      = (const float*)d_in[15];
    float* out = (float*)d_out;

    float *cur, *ctxpre, *ctx, *s, *gi, *gh, *nbr, *acat;
    cudaGetSymbolAddress((void**)&cur,    g_cur);
    cudaGetSymbolAddress((void**)&ctxpre, g_ctxpre);
    cudaGetSymbolAddress((void**)&ctx,    g_ctx);
    cudaGetSymbolAddress((void**)&s,      g_s);
    cudaGetSymbolAddress((void**)&gi,     g_gi);
    cudaGetSymbolAddress((void**)&gh,     g_gh);
    cudaGetSymbolAddress((void**)&nbr,    g_nbr);
    cudaGetSymbolAddress((void**)&acat,   g_acat);

    const int KC = FA_ + FB_;

    // 1. cur = leaky(atom_list @ atom_W^T + atom_b)         [32768 x 200, K=39]
    sgemm_tc<1,0><<<dim3(ceil_div(FF, TBN), MROWS / TBM), 256>>>(
        atom_list, atom_W, atom_b, nullptr, cur, MROWS, FF, FA_);

    // 2. gather concat inputs for neighbor embedding
    gather_acat_kernel<<<ceil_div(MSLOT * KC, 256), 256>>>(
        atom_list, bond_list, adeg, bdeg, acat);

    // 3. nbrfeat = leaky(acat @ nbr_W^T + nbr_b)            [196608 x 200, K=49]
    sgemm_tc<1,0><<<dim3(ceil_div(FF, TBN), MSLOT / TBM), 256>>>(
        acat, nbr_W, nbr_b, nullptr, nbr, MSLOT, FF, KC);

    for (int d = 0; d < RR; d++) {
        // attention: ctxpre + per-row attn sum
        attention_kernel<<<MROWS / 8, 256>>>(
            cur, nbr, adeg,
            align_W + (size_t)d * 2 * FF, align_b + d,
            ctxpre, s, (d == 0) ? 1 : 0);

        // context = elu(ctxpre @ attend_W^T + attend_b * s) [32768 x 200, K=200]
        sgemm_tc<2,1><<<dim3(ceil_div(FF, TBN), MROWS / TBM), 256>>>(
            ctxpre, attend_W + (size_t)d * FF * FF, attend_b + (size_t)d * FF, s,
            ctx, MROWS, FF, FF);

        // gi = context @ Wih^T + bih                        [32768 x 600, K=200]
        sgemm_tc<0,1><<<dim3(ceil_div(3 * FF, TBN), MROWS / TBM), 256>>>(
            ctx, gWih + (size_t)d * 3 * FF * FF, gbih + (size_t)d * 3 * FF, nullptr,
            gi, MROWS, 3 * FF, FF);

        // gh = cur @ Whh^T + bhh
        sgemm_tc<0,1><<<dim3(ceil_div(3 * FF, TBN), MROWS / TBM), 256>>>(
            cur, gWhh + (size_t)d * 3 * FF * FF, gbhh + (size_t)d * 3 * FF, nullptr,
            gh, MROWS, 3 * FF, FF);

        // pointwise GRU + relu; final round writes to d_out
        gru_kernel<<<ceil_div(MROWS * FF, 256), 256>>>(
            gi, gh, cur, (d == RR - 1) ? out : cur);
    }
}

// round 8
// speedup vs baseline: 1.2510x; 1.2510x over previous
#include <cuda_runtime.h>
#include <cstddef>

// Problem constants
#define BATCH 256
#define LSEQ  128
#define DD    6
#define FF    200
#define FA_   39
#define FB_   10
#define RR    2
#define MROWS (BATCH*LSEQ)          // 32768
#define MSLOT (MROWS*DD)            // 196608
#define KC    (FA_+FB_)             // 49

// ---------------- scratch (device globals; no allocations allowed) ----------
__device__ float g_cur   [(size_t)MROWS*FF];
__device__ float g_ctxpre[(size_t)MROWS*FF];
__device__ float g_ctx   [(size_t)MROWS*FF];
__device__ float g_s     [MROWS];
__device__ float g_gi    [(size_t)MROWS*3*FF];
__device__ float g_gh    [(size_t)MROWS*3*FF];
__device__ float g_nbr   [(size_t)MSLOT*FF];
__device__ float g_acat  [(size_t)MSLOT*KC];
// tf32-pre-rounded copies of mma operands
__device__ float g_atomr [(size_t)MROWS*FA_];
__device__ float g_atomW [FF*FA_];
__device__ float g_nbrW  [FF*KC];
__device__ float g_attW  [RR*FF*FF];
__device__ float g_Wih   [(size_t)RR*3*FF*FF];
__device__ float g_Whh   [(size_t)RR*3*FF*FF];

__device__ __forceinline__ unsigned f2tf32(float x) {
    unsigned r;
    asm("cvt.rna.tf32.f32 %0, %1;" : "=r"(r) : "f"(x));
    return r;
}
__device__ __forceinline__ float roundtf(float x) { return __uint_as_float(f2tf32(x)); }

__device__ __forceinline__ void mma_tf32(float* c,
                                         unsigned a0, unsigned a1, unsigned a2, unsigned a3,
                                         unsigned b0, unsigned b1) {
    asm volatile(
        "mma.sync.aligned.m16n8k8.row.col.f32.tf32.tf32.f32 "
        "{%0,%1,%2,%3}, {%4,%5,%6,%7}, {%8,%9}, {%0,%1,%2,%3};"
        : "+f"(c[0]), "+f"(c[1]), "+f"(c[2]), "+f"(c[3])
        : "r"(a0), "r"(a1), "r"(a2), "r"(a3), "r"(b0), "r"(b1));
}

// cp.async helpers
__device__ __forceinline__ void cpa16(float* dst, const float* src, int bytes) {
    unsigned d = (unsigned)__cvta_generic_to_shared(dst);
    asm volatile("cp.async.cg.shared.global [%0], [%1], 16, %2;\n"
                 :: "r"(d), "l"(src), "r"(bytes));
}
__device__ __forceinline__ void cpa4(float* dst, const float* src, int bytes) {
    unsigned d = (unsigned)__cvta_generic_to_shared(dst);
    asm volatile("cp.async.ca.shared.global [%0], [%1], 4, %2;\n"
                 :: "r"(d), "l"(src), "r"(bytes));
}
__device__ __forceinline__ void cp_commit() { asm volatile("cp.async.commit_group;\n"); }

// =================== tf32 tensor-core SGEMM v3 (cp.async pipelined) =========
//   C[M,N] = act(A[M,K] @ W[N,K]^T + bias[N]*rowscale[M])
//   ACT: 0=none, 1=leaky_relu(0.01), 2=elu.  ROUND: round output to tf32.
//   VEC=1 requires K%4==0 (16B cp.async); VEC=0 uses 4B cp.async.
// BM=BN=128, BK=16, 3 stages (48KB static smem), 8 warps (2M x 4N), warp 64x32.
// Smem swizzle: 16B chunk t of row m stored at chunk t ^ ((m>>1)&3).
#define SBM 128
#define SBN 128
#define SBK 16
#define NSTAGE 3

__device__ __forceinline__ void cp_wait_1() {
    asm volatile("cp.async.wait_group 1;\n");
}

template<int ACT, int ROUND, int VEC>
__global__ void __launch_bounds__(256, 2)
sgemm_tc(const float* __restrict__ A, const float* __restrict__ W,
         const float* __restrict__ bias, const float* __restrict__ rowscale,
         float* __restrict__ C, int M, int N, int K)
{
    __shared__ __align__(16) float As[NSTAGE][SBM][SBK];
    __shared__ __align__(16) float Bs[NSTAGE][SBN][SBK];

    const int tid   = threadIdx.x;
    const int lane  = tid & 31;
    const int warp  = tid >> 5;
    const int warpM = warp & 1;         // 0..1 (M 64 each)
    const int warpN = warp >> 1;        // 0..3 (N 32 each)
    const int mBase = blockIdx.y * SBM;
    const int nBase = blockIdx.x * SBN;
    const int nk    = (K + SBK - 1) / SBK;
    const int r0 = lane >> 2;
    const int c0 = lane & 3;
    const int sw = (r0 >> 1) & 3;       // fragment swizzle (constant per thread)

    float acc[4][4][4];
    #pragma unroll
    for (int mt = 0; mt < 4; mt++)
        #pragma unroll
        for (int nt = 0; nt < 4; nt++)
            #pragma unroll
            for (int i = 0; i < 4; i++) acc[mt][nt][i] = 0.f;

#define LOAD(S, KT)                                                            \
    {                                                                          \
        int kbase = (KT) * SBK;                                                \
        if (VEC) {                                                             \
            _Pragma("unroll")                                                  \
            for (int i = 0; i < 2; i++) {                                      \
                int e = tid + i * 256;                                         \
                int m = e >> 2, t = e & 3;                                     \
                int gk = kbase + t * 4;                                        \
                int rem = K - gk;                                              \
                int bytes = rem >= 4 ? 16 : (rem > 0 ? rem * 4 : 0);           \
                const float* src = A + (size_t)(mBase + m) * K                 \
                                     + (bytes ? gk : 0);                       \
                cpa16(&As[S][m][(t ^ ((m >> 1) & 3)) << 2], src, bytes);       \
            }                                                                  \
            _Pragma("unroll")                                                  \
            for (int i = 0; i < 2; i++) {                                      \
                int e = tid + i * 256;                                         \
                int n = e >> 2, t = e & 3;                                     \
                int gn = nBase + n, gk = kbase + t * 4;                        \
                int rem = K - gk;                                              \
                int bytes = (gn < N) ? (rem >= 4 ? 16                          \
                                                 : (rem > 0 ? rem * 4 : 0))    \
                                     : 0;                                      \
                const float* src = W + (size_t)(gn < N ? gn : 0) * K           \
                                     + (bytes ? gk : 0);                       \
                cpa16(&Bs[S][n][(t ^ ((n >> 1) & 3)) << 2], src, bytes);       \
            }                                                                  \
        } else {                                                               \
            _Pragma("unroll")                                                  \
            for (int i = 0; i < 8; i++) {                                      \
                int e = tid + i * 256;                                         \
                int m = e >> 4, k = e & 15;                                    \
                int gk = kbase + k;                                            \
                int bytes = (gk < K) ? 4 : 0;                                  \
                const float* src = A + (size_t)(mBase + m) * K                 \
                                     + (bytes ? gk : 0);                       \
                cpa4(&As[S][m][((((k >> 2) ^ ((m >> 1) & 3)) << 2) + (k & 3))],\
                     src, bytes);                                              \
            }                                                                  \
            _Pragma("unroll")                                                  \
            for (int i = 0; i < 8; i++) {                                      \
                int e = tid + i * 256;                                         \
                int n = e >> 4, k = e & 15;                                    \
                int gn = nBase + n, gk = kbase + k;                            \
                int bytes = (gn < N && gk < K) ? 4 : 0;                        \
                const float* src = W + (size_t)(gn < N ? gn : 0) * K           \
                                     + (bytes ? gk : 0);                       \
                cpa4(&Bs[S][n][((((k >> 2) ^ ((n >> 1) & 3)) << 2) + (k & 3))],\
                     src, bytes);                                              \
            }                                                                  \
        }                                                                      \
        cp_commit();                                                           \
    }

    // prologue: stages 0..NSTAGE-2
    #pragma unroll
    for (int s = 0; s < NSTAGE - 1; s++) {
        if (s < nk) { LOAD(s, s); } else { cp_commit(); }
    }

    for (int kt = 0; kt < nk; kt++) {
        const int s = kt % NSTAGE;
        cp_wait_1();                 // load for tile kt complete
        __syncthreads();             // all warps past tile kt-1 reads

        int ktn = kt + NSTAGE - 1;
        if (ktn < nk) { LOAD(ktn % NSTAGE, ktn); } else { cp_commit(); }

        const float (*as)[SBK] = As[s];
        const float (*bs)[SBK] = Bs[s];
        const int w[4] = { ((0 ^ sw) << 2) + c0, ((1 ^ sw) << 2) + c0,
                           ((2 ^ sw) << 2) + c0, ((3 ^ sw) << 2) + c0 };

        #pragma unroll
        for (int kk = 0; kk < 2; kk++) {
            const int wa = w[2 * kk], wb = w[2 * kk + 1];
            unsigned a[4][4], b[4][2];
            #pragma unroll
            for (int mt = 0; mt < 4; mt++) {
                int r1 = warpM * 64 + mt * 16 + r0;
                a[mt][0] = __float_as_uint(as[r1    ][wa]);
                a[mt][1] = __float_as_uint(as[r1 + 8][wa]);
                a[mt][2] = __float_as_uint(as[r1    ][wb]);
                a[mt][3] = __float_as_uint(as[r1 + 8][wb]);
            }
            #pragma unroll
            for (int nt = 0; nt < 4; nt++) {
                int rb = warpN * 32 + nt * 8 + r0;
                b[nt][0] = __float_as_uint(bs[rb][wa]);
                b[nt][1] = __float_as_uint(bs[rb][wb]);
            }
            #pragma unroll
            for (int mt = 0; mt < 4; mt++)
                #pragma unroll
                for (int nt = 0; nt < 4; nt++)
                    mma_tf32(acc[mt][nt],
                             a[mt][0], a[mt][1], a[mt][2], a[mt][3],
                             b[nt][0], b[nt][1]);
        }
    }

    // -------- epilogue --------
    #pragma unroll
    for (int mt = 0; mt < 4; mt++) {
        int row0 = mBase + warpM * 64 + mt * 16 + r0;
        float s0 = rowscale ? rowscale[row0]     : 1.f;
        float s1 = rowscale ? rowscale[row0 + 8] : 1.f;
        #pragma unroll
        for (int nt = 0; nt < 4; nt++) {
            int col0 = nBase + warpN * 32 + nt * 8 + c0 * 2;
            #pragma unroll
            for (int j = 0; j < 2; j++) {
                int col = col0 + j;
                if (col < N) {
                    float bv = bias[col];
                    float v0 = acc[mt][nt][j]     + bv * s0;
                    float v1 = acc[mt][nt][j + 2] + bv * s1;
                    if (ACT == 1) {
                        v0 = (v0 > 0.f) ? v0 : 0.01f * v0;
                        v1 = (v1 > 0.f) ? v1 : 0.01f * v1;
                    } else if (ACT == 2) {
                        v0 = (v0 > 0.f) ? v0 : expm1f(v0);
                        v1 = (v1 > 0.f) ? v1 : expm1f(v1);
                    }
                    if (ROUND) { v0 = roundtf(v0); v1 = roundtf(v1); }
                    C[(size_t)row0 * N + col]       = v0;
                    C[(size_t)(row0 + 8) * N + col] = v1;
                }
            }
        }
    }
#undef LOAD
}

// ---------------- tf32 pre-round copy ---------------------------------------
__global__ void round_copy(const float* __restrict__ in, float* __restrict__ out, int n)
{
    int i = blockIdx.x * blockDim.x + threadIdx.x;
    if (i < n) out[i] = __uint_as_float(f2tf32(in[i]));
}

// ---------------- gather concat(atom_nbr, bond_nbr) into [MSLOT, 49] --------
// output tf32-rounded (feeds mma A operand)
__global__ void gather_acat_kernel(const float* __restrict__ atom_list,
                                   const float* __restrict__ bond_list,
                                   const int*   __restrict__ adeg,
                                   const int*   __restrict__ bdeg,
                                   float* __restrict__ acat)
{
    int e = blockIdx.x * blockDim.x + threadIdx.x;
    if (e >= MSLOT * KC) return;
    int slot = e / KC;
    int k    = e - slot * KC;
    int b    = slot / (LSEQ * DD);
    float v;
    if (k < FA_) {
        int a = adeg[slot];
        v = atom_list[((size_t)b * LSEQ + a) * FA_ + k];
    } else {
        int bb = bdeg[slot];
        v = bond_list[((size_t)b * LSEQ + bb) * FB_ + (k - FA_)];
    }
    acat[e] = __uint_as_float(f2tf32(v));
}

// ---------------- attention: warp per row (ctxpre rounded to tf32) ----------
__global__ void __launch_bounds__(256)
attention_kernel(const float* __restrict__ cur,
                 const float* __restrict__ nbrfeat,
                 const int*   __restrict__ adeg,
                 const float* __restrict__ alignW,
                 const float* __restrict__ alignB,
                 float* __restrict__ ctxpre,
                 float* __restrict__ srow,
                 int first)
{
    int gw   = (blockIdx.x * blockDim.x + threadIdx.x) >> 5;
    int lane = threadIdx.x & 31;
    if (gw >= MROWS) return;
    const int r = gw;
    const int b = r >> 7;
    const float ab = alignB[0];

    float cv[7], a0[7], a1[7];
    #pragma unroll
    for (int i = 0; i < 7; i++) {
        int idx = lane + 32 * i;
        bool ok = idx < FF;
        cv[i] = ok ? cur[(size_t)r * FF + idx] : 0.f;
        a0[i] = ok ? alignW[idx]       : 0.f;
        a1[i] = ok ? alignW[FF + idx]  : 0.f;
    }
    float qd = 0.f;
    #pragma unroll
    for (int i = 0; i < 7; i++) qd += cv[i] * a0[i];
    #pragma unroll
    for (int o = 16; o > 0; o >>= 1) qd += __shfl_xor_sync(0xffffffffu, qd, o);

    float nv[DD][7];
    float score[DD];
    int   nai[DD];

    #pragma unroll
    for (int d = 0; d < DD; d++) {
        int na = adeg[r * DD + d];
        nai[d] = na;
        const float* np = first ? (nbrfeat + ((size_t)r * DD + d) * FF)
                                : (cur + ((size_t)(b * LSEQ + na)) * FF);
        float nd = 0.f;
        #pragma unroll
        for (int i = 0; i < 7; i++) {
            int idx = lane + 32 * i;
            float v = (idx < FF) ? np[idx] : 0.f;
            nv[d][i] = v;
            nd += v * a1[i];
        }
        #pragma unroll
        for (int o = 16; o > 0; o >>= 1) nd += __shfl_xor_sync(0xffffffffu, nd, o);
        float sc = qd + nd + ab;
        sc = (sc > 0.f) ? sc : 0.01f * sc;
        if (na == LSEQ - 1) sc = sc - 9e8f;
        score[d] = sc;
    }

    float mx = score[0];
    #pragma unroll
    for (int d = 1; d < DD; d++) mx = fmaxf(mx, score[d]);
    float e[DD], den = 0.f;
    #pragma unroll
    for (int d = 0; d < DD; d++) { e[d] = expf(score[d] - mx); den += e[d]; }
    float inv = 1.f / den;
    float s = 0.f;
    #pragma unroll
    for (int d = 0; d < DD; d++) {
        float a = e[d] * inv;
        if (nai[d] == LSEQ - 1) a = 0.f;
        e[d] = a;
        s += a;
    }

    #pragma unroll
    for (int i = 0; i < 7; i++) {
        int idx = lane + 32 * i;
        if (idx < FF) {
            float v = 0.f;
            #pragma unroll
            for (int d = 0; d < DD; d++) v += e[d] * nv[d][i];
            ctxpre[(size_t)r * FF + idx] = __uint_as_float(f2tf32(v));
        }
    }
    if (lane == 0) srow[r] = s;
}

// ---------------- GRU pointwise ---------------------------------------------
__global__ void gru_kernel(const float* __restrict__ gi, const float* __restrict__ gh,
                           const float* __restrict__ cur, float* __restrict__ out,
                           int rnd)
{
    int idx = blockIdx.x * blockDim.x + threadIdx.x;
    if (idx >= MROWS * FF) return;
    int r = idx / FF;
    int j = idx - r * FF;
    size_t base = (size_t)r * 3 * FF + j;
    float ir = gi[base], iz = gi[base + FF], in_ = gi[base + 2 * FF];
    float hr = gh[base], hz = gh[base + FF], hn  = gh[base + 2 * FF];
    float rr = 1.f / (1.f + expf(-(ir + hr)));
    float z  = 1.f / (1.f + expf(-(iz + hz)));
    float n  = tanhf(in_ + rr * hn);
    float c  = cur[idx];
    float h  = (1.f - z) * n + z * c;
    h = (h > 0.f) ? h : 0.f;
    out[idx] = rnd ? __uint_as_float(f2tf32(h)) : h;
}

// ---------------- launch ------------------------------------------------------
static inline int ceil_div(int a, int b) { return (a + b - 1) / b; }

extern "C" void kernel_launch(void* const* d_in, const int* in_sizes, int n_in,
                              void* d_out, int out_size)
{
    const float* atom_list = (const float*)d_in[0];
    const float* bond_list = (const float*)d_in[1];
    const int*   adeg      = (const int*)  d_in[2];
    const int*   bdeg      = (const int*)  d_in[3];
    const float* atom_W    = (const float*)d_in[4];
    const float* atom_b    = (const float*)d_in[5];
    const float* nbr_W     = (const float*)d_in[6];
    const float* nbr_b     = (const float*)d_in[7];
    const float* align_W   = (const float*)d_in[8];
    const float* align_b   = (const float*)d_in[9];
    const float* attend_W  = (const float*)d_in[10];
    const float* attend_b  = (const float*)d_in[11];
    const float* gWih      = (const float*)d_in[12];
    const float* gWhh      = (const float*)d_in[13];
    const float* gbih      = (const float*)d_in[14];
    const float* gbhh      = (const float*)d_in[15];
    float* out = (float*)d_out;

    float *cur, *ctxpre, *ctx, *s, *gi, *gh, *nbr, *acat;
    float *atomr, *atomWr, *nbrWr, *attWr, *Wihr, *Whhr;
    cudaGetSymbolAddress((void**)&cur,    g_cur);
    cudaGetSymbolAddress((void**)&ctxpre, g_ctxpre);
    cudaGetSymbolAddress((void**)&ctx,    g_ctx);
    cudaGetSymbolAddress((void**)&s,      g_s);
    cudaGetSymbolAddress((void**)&gi,     g_gi);
    cudaGetSymbolAddress((void**)&gh,     g_gh);
    cudaGetSymbolAddress((void**)&nbr,    g_nbr);
    cudaGetSymbolAddress((void**)&acat,   g_acat);
    cudaGetSymbolAddress((void**)&atomr,  g_atomr);
    cudaGetSymbolAddress((void**)&atomWr, g_atomW);
    cudaGetSymbolAddress((void**)&nbrWr,  g_nbrW);
    cudaGetSymbolAddress((void**)&attWr,  g_attW);
    cudaGetSymbolAddress((void**)&Wihr,   g_Wih);
    cudaGetSymbolAddress((void**)&Whhr,   g_Whh);

    // ---- pre-round all mma operands to tf32 (scratch copies) ----
    round_copy<<<ceil_div(MROWS * FA_, 256), 256>>>(atom_list, atomr, MROWS * FA_);
    round_copy<<<ceil_div(FF * FA_, 256), 256>>>(atom_W, atomWr, FF * FA_);
    round_copy<<<ceil_div(FF * KC, 256), 256>>>(nbr_W, nbrWr, FF * KC);
    round_copy<<<ceil_div(RR * FF * FF, 256), 256>>>(attend_W, attWr, RR * FF * FF);
    round_copy<<<ceil_div(RR * 3 * FF * FF, 256), 256>>>(gWih, Wihr, RR * 3 * FF * FF);
    round_copy<<<ceil_div(RR * 3 * FF * FF, 256), 256>>>(gWhh, Whhr, RR * 3 * FF * FF);

    // 1. cur = leaky(atom_list @ atom_W^T + atom_b)   [32768 x 200, K=39]
    sgemm_tc<1, 1, 0><<<dim3(ceil_div(FF, SBN), MROWS / SBM), 256>>>(
        atomr, atomWr, atom_b, nullptr, cur, MROWS, FF, FA_);

    // 2. gather concat inputs (rounded)
    gather_acat_kernel<<<ceil_div(MSLOT * KC, 256), 256>>>(
        atom_list, bond_list, adeg, bdeg, acat);

    // 3. nbrfeat = leaky(acat @ nbr_W^T + nbr_b)      [196608 x 200, K=49]
    sgemm_tc<1, 0, 0><<<dim3(ceil_div(FF, SBN), MSLOT / SBM), 256>>>(
        acat, nbrWr, nbr_b, nullptr, nbr, MSLOT, FF, KC);

    for (int d = 0; d < RR; d++) {
        attention_kernel<<<MROWS / 8, 256>>>(
            cur, nbr, adeg,
            align_W + (size_t)d * 2 * FF, align_b + d,
            ctxpre, s, (d == 0) ? 1 : 0);

        // context = elu(ctxpre @ attend_W^T + attend_b * s)  [32768 x 200, K=200]
        sgemm_tc<2, 1, 1><<<dim3(ceil_div(FF, SBN), MROWS / SBM), 256>>>(
            ctxpre, attWr + (size_t)d * FF * FF, attend_b + (size_t)d * FF, s,
            ctx, MROWS, FF, FF);

        // gi = context @ Wih^T + bih                        [32768 x 600, K=200]
        sgemm_tc<0, 0, 1><<<dim3(ceil_div(3 * FF, SBN), MROWS / SBM), 256>>>(
            ctx, Wihr + (size_t)d * 3 * FF * FF, gbih + (size_t)d * 3 * FF, nullptr,
            gi, MROWS, 3 * FF, FF);

        // gh = cur @ Whh^T + bhh
        sgemm_tc<0, 0, 1><<<dim3(ceil_div(3 * FF, SBN), MROWS / SBM), 256>>>(
            cur, Whhr + (size_t)d * 3 * FF * FF, gbhh + (size_t)d * 3 * FF, nullptr,
            gh, MROWS, 3 * FF, FF);

        gru_kernel<<<ceil_div(MROWS * FF, 256), 256>>>(
            gi, gh, cur, (d == RR - 1) ? out : cur, (d < RR - 1) ? 1 : 0);
    }
}

// round 9
// speedup vs baseline: 1.4857x; 1.1877x over previous
#include <cuda_runtime.h>
#include <cuda_fp16.h>
#include <cstddef>

// Problem constants
#define BATCH 256
#define LSEQ  128
#define DD    6
#define FF    200
#define FA_   39
#define FB_   10
#define RR    2
#define MROWS (BATCH*LSEQ)          // 32768
#define MSLOT (MROWS*DD)            // 196608
#define KC    (FA_+FB_)             // 49
#define KPA   40                    // padded K for atom GEMM (16B-aligned rows)
#define KPC   56                    // padded K for nbr GEMM
#define KPF   200                   // F (already 16B-aligned: 400B)

// ---------------- scratch (device globals; no allocations allowed) ----------
__device__ __half h_cur   [(size_t)MROWS*FF];
__device__ __half h_ctxpre[(size_t)MROWS*FF];
__device__ __half h_ctx   [(size_t)MROWS*FF];
__device__ float  g_s     [MROWS];
__device__ float  g_gi    [(size_t)MROWS*3*FF];
__device__ float  g_gh    [(size_t)MROWS*3*FF];
__device__ __half h_nbr   [(size_t)MSLOT*FF];
__device__ __half h_acat  [(size_t)MSLOT*KPC];
__device__ __half h_atom  [(size_t)MROWS*KPA];
__device__ __half h_atomW [FF*KPA];
__device__ __half h_nbrW  [FF*KPC];
__device__ __half h_attW  [RR*FF*FF];
__device__ __half h_Wih   [(size_t)RR*3*FF*FF];
__device__ __half h_Whh   [(size_t)RR*3*FF*FF];

// ---------------- PTX helpers ------------------------------------------------
__device__ __forceinline__ void mma_f16(float* c, const unsigned* a, const unsigned* b) {
    asm volatile(
        "mma.sync.aligned.m16n8k16.row.col.f32.f16.f16.f32 "
        "{%0,%1,%2,%3}, {%4,%5,%6,%7}, {%8,%9}, {%0,%1,%2,%3};"
        : "+f"(c[0]), "+f"(c[1]), "+f"(c[2]), "+f"(c[3])
        : "r"(a[0]), "r"(a[1]), "r"(a[2]), "r"(a[3]), "r"(b[0]), "r"(b[1]));
}

__device__ __forceinline__ void ldsm4(unsigned& r0, unsigned& r1, unsigned& r2, unsigned& r3,
                                      const void* p) {
    unsigned addr = (unsigned)__cvta_generic_to_shared(p);
    asm volatile("ldmatrix.sync.aligned.m8n8.x4.shared.b16 {%0,%1,%2,%3}, [%4];"
                 : "=r"(r0), "=r"(r1), "=r"(r2), "=r"(r3) : "r"(addr));
}

__device__ __forceinline__ void cpa16h(__half* dst, const __half* src, int bytes) {
    unsigned d = (unsigned)__cvta_generic_to_shared(dst);
    asm volatile("cp.async.cg.shared.global [%0], [%1], 16, %2;\n"
                 :: "r"(d), "l"(src), "r"(bytes));
}
__device__ __forceinline__ void cp_commit() { asm volatile("cp.async.commit_group;\n"); }
__device__ __forceinline__ void cp_wait_1() { asm volatile("cp.async.wait_group 1;\n"); }

// =================== fp16 tensor-core GEMM (cp.async + ldmatrix) ============
//   C[M,N] = act(A[M,Kp] @ W[N,Kp]^T + bias[N]*rowscale[M])
//   A, W are __half with rows padded to Kp (multiple of 8, zero-padded).
//   ACT: 0=none, 1=leaky_relu(0.01), 2=elu.  OUTH: 1 -> store __half.
// BM=BN=128, BK=16 halves, 3 stages, 8 warps (2M x 4N), warp 64x32.
// Smem: row = 16 halves (2 x 16B chunks); chunk c of row m stored at c^((m>>2)&1).
#define SBM 128
#define SBN 128
#define NSTAGE 3

template<int ACT, int OUTH>
__global__ void __launch_bounds__(256, 2)
gemm_h(const __half* __restrict__ A, const __half* __restrict__ W,
       const float* __restrict__ bias, const float* __restrict__ rowscale,
       void* __restrict__ Cv, int M, int N, int Kp)
{
    __shared__ __align__(16) __half As[NSTAGE][SBM][16];
    __shared__ __align__(16) __half Bs[NSTAGE][SBN][16];

    const int tid   = threadIdx.x;
    const int lane  = tid & 31;
    const int warp  = tid >> 5;
    const int warpM = warp & 1;         // 0..1 (64 rows each)
    const int warpN = warp >> 1;        // 0..3 (32 cols each)
    const int mBase = blockIdx.y * SBM;
    const int nBase = blockIdx.x * SBN;
    const int nk    = (Kp + 15) / 16;
    const int r0 = lane >> 2;
    const int c0 = lane & 3;
    // ldmatrix lane addressing
    const int lrowA = ((lane >> 3) & 1) * 8 + (lane & 7);  // row offset in 16
    const int lchA  = lane >> 4;                           // chunk 0/1
    const int lrowB = (lane >> 4) * 8 + (lane & 7);        // row offset in 16
    const int lchB  = (lane >> 3) & 1;

    float acc[4][4][4];
    #pragma unroll
    for (int mt = 0; mt < 4; mt++)
        #pragma unroll
        for (int nt = 0; nt < 4; nt++)
            #pragma unroll
            for (int i = 0; i < 4; i++) acc[mt][nt][i] = 0.f;

#define LOAD(S, KT)                                                            \
    {                                                                          \
        int kbase = (KT) * 16;                                                 \
        {                                                                      \
            int m = tid >> 1, c = tid & 1;                                     \
            int k0 = kbase + c * 8;                                            \
            int bytes = (k0 < Kp) ? 16 : 0;                                    \
            const __half* src = A + (size_t)(mBase + m) * Kp + (bytes ? k0 : 0);\
            cpa16h(&As[S][m][(c ^ ((m >> 2) & 1)) * 8], src, bytes);           \
        }                                                                      \
        {                                                                      \
            int n = tid >> 1, c = tid & 1;                                     \
            int gn = nBase + n, k0 = kbase + c * 8;                            \
            int bytes = (gn < N && k0 < Kp) ? 16 : 0;                          \
            const __half* src = W + (size_t)(gn < N ? gn : 0) * Kp             \
                                  + (bytes ? k0 : 0);                          \
            cpa16h(&Bs[S][n][(c ^ ((n >> 2) & 1)) * 8], src, bytes);           \
        }                                                                      \
        cp_commit();                                                           \
    }

    #pragma unroll
    for (int s = 0; s < NSTAGE - 1; s++) {
        if (s < nk) { LOAD(s, s); } else { cp_commit(); }
    }

    for (int kt = 0; kt < nk; kt++) {
        const int st = kt % NSTAGE;
        cp_wait_1();
        __syncthreads();

        int ktn = kt + NSTAGE - 1;
        if (ktn < nk) { LOAD(ktn % NSTAGE, ktn); } else { cp_commit(); }

        const __half (*as)[16] = As[st];
        const __half (*bs)[16] = Bs[st];

        unsigned a[4][4];
        #pragma unroll
        for (int mt = 0; mt < 4; mt++) {
            int row = warpM * 64 + mt * 16 + lrowA;
            int swc = lchA ^ ((row >> 2) & 1);
            ldsm4(a[mt][0], a[mt][1], a[mt][2], a[mt][3], &as[row][swc * 8]);
        }
        unsigned b[4][2];
        #pragma unroll
        for (int p = 0; p < 2; p++) {
            int row = warpN * 32 + p * 16 + lrowB;
            int swc = lchB ^ ((row >> 2) & 1);
            unsigned t0, t1, t2, t3;
            ldsm4(t0, t1, t2, t3, &bs[row][swc * 8]);
            b[2 * p][0]     = t0; b[2 * p][1]     = t1;
            b[2 * p + 1][0] = t2; b[2 * p + 1][1] = t3;
        }
        #pragma unroll
        for (int mt = 0; mt < 4; mt++)
            #pragma unroll
            for (int nt = 0; nt < 4; nt++)
                mma_f16(acc[mt][nt], a[mt], b[nt]);
    }

    // -------- epilogue --------
    float*  Cf = (float*)Cv;
    __half* Ch = (__half*)Cv;
    #pragma unroll
    for (int mt = 0; mt < 4; mt++) {
        int row0 = mBase + warpM * 64 + mt * 16 + r0;
        float s0 = rowscale ? rowscale[row0]     : 1.f;
        float s1 = rowscale ? rowscale[row0 + 8] : 1.f;
        #pragma unroll
        for (int nt = 0; nt < 4; nt++) {
            int col0 = nBase + warpN * 32 + nt * 8 + c0 * 2;
            #pragma unroll
            for (int j = 0; j < 2; j++) {
                int col = col0 + j;
                if (col < N) {
                    float bv = bias[col];
                    float v0 = acc[mt][nt][j]     + bv * s0;
                    float v1 = acc[mt][nt][j + 2] + bv * s1;
                    if (ACT == 1) {
                        v0 = (v0 > 0.f) ? v0 : 0.01f * v0;
                        v1 = (v1 > 0.f) ? v1 : 0.01f * v1;
                    } else if (ACT == 2) {
                        v0 = (v0 > 0.f) ? v0 : expm1f(v0);
                        v1 = (v1 > 0.f) ? v1 : expm1f(v1);
                    }
                    if (OUTH) {
                        Ch[(size_t)row0 * N + col]       = __float2half_rn(v0);
                        Ch[(size_t)(row0 + 8) * N + col] = __float2half_rn(v1);
                    } else {
                        Cf[(size_t)row0 * N + col]       = v0;
                        Cf[(size_t)(row0 + 8) * N + col] = v1;
                    }
                }
            }
        }
    }
#undef LOAD
}

// ---------------- fp32 -> padded fp16 copy (weights / atom_list) ------------
__global__ void w2h_pad(const float* __restrict__ in, __half* __restrict__ out,
                        int N, int K, int Kp)
{
    int i = blockIdx.x * blockDim.x + threadIdx.x;
    if (i >= N * Kp) return;
    int n = i / Kp, k = i - n * Kp;
    out[i] = (k < K) ? __float2half_rn(in[(size_t)n * K + k]) : __half(0.f);
}

// ---------------- gather concat(atom_nbr, bond_nbr) -> half [MSLOT, KPC] ----
__global__ void gather_acat_kernel(const float* __restrict__ atom_list,
                                   const float* __restrict__ bond_list,
                                   const int*   __restrict__ adeg,
                                   const int*   __restrict__ bdeg,
                                   __half* __restrict__ acat)
{
    int e = blockIdx.x * blockDim.x + threadIdx.x;
    if (e >= MSLOT * KPC) return;
    int slot = e / KPC;
    int k    = e - slot * KPC;
    int b    = slot / (LSEQ * DD);
    float v = 0.f;
    if (k < FA_) {
        int a = adeg[slot];
        v = atom_list[((size_t)b * LSEQ + a) * FA_ + k];
    } else if (k < KC) {
        int bb = bdeg[slot];
        v = bond_list[((size_t)b * LSEQ + bb) * FB_ + (k - FA_)];
    }
    acat[e] = __float2half_rn(v);
}

// ---------------- attention: warp per row (half in, half out) ---------------
__global__ void __launch_bounds__(256)
attention_kernel(const __half* __restrict__ cur,
                 const __half* __restrict__ nbrfeat,
                 const int*    __restrict__ adeg,
                 const float*  __restrict__ alignW,
                 const float*  __restrict__ alignB,
                 __half* __restrict__ ctxpre,
                 float*  __restrict__ srow,
                 int first)
{
    int gw   = (blockIdx.x * blockDim.x + threadIdx.x) >> 5;
    int lane = threadIdx.x & 31;
    if (gw >= MROWS) return;
    const int r = gw;
    const int b = r >> 7;
    const float ab = alignB[0];

    float cv[7], a0[7], a1[7];
    #pragma unroll
    for (int i = 0; i < 7; i++) {
        int idx = lane + 32 * i;
        bool ok = idx < FF;
        cv[i] = ok ? __half2float(cur[(size_t)r * FF + idx]) : 0.f;
        a0[i] = ok ? alignW[idx]      : 0.f;
        a1[i] = ok ? alignW[FF + idx] : 0.f;
    }
    float qd = 0.f;
    #pragma unroll
    for (int i = 0; i < 7; i++) qd += cv[i] * a0[i];
    #pragma unroll
    for (int o = 16; o > 0; o >>= 1) qd += __shfl_xor_sync(0xffffffffu, qd, o);

    float nv[DD][7];
    float score[DD];
    int   nai[DD];

    #pragma unroll
    for (int d = 0; d < DD; d++) {
        int na = adeg[r * DD + d];
        nai[d] = na;
        const __half* np = first ? (nbrfeat + ((size_t)r * DD + d) * FF)
                                 : (cur + ((size_t)(b * LSEQ + na)) * FF);
        float nd = 0.f;
        #pragma unroll
        for (int i = 0; i < 7; i++) {
            int idx = lane + 32 * i;
            float v = (idx < FF) ? __half2float(np[idx]) : 0.f;
            nv[d][i] = v;
            nd += v * a1[i];
        }
        #pragma unroll
        for (int o = 16; o > 0; o >>= 1) nd += __shfl_xor_sync(0xffffffffu, nd, o);
        float sc = qd + nd + ab;
        sc = (sc > 0.f) ? sc : 0.01f * sc;
        if (na == LSEQ - 1) sc = sc - 9e8f;
        score[d] = sc;
    }

    float mx = score[0];
    #pragma unroll
    for (int d = 1; d < DD; d++) mx = fmaxf(mx, score[d]);
    float e[DD], den = 0.f;
    #pragma unroll
    for (int d = 0; d < DD; d++) { e[d] = expf(score[d] - mx); den += e[d]; }
    float inv = 1.f / den;
    float s = 0.f;
    #pragma unroll
    for (int d = 0; d < DD; d++) {
        float a = e[d] * inv;
        if (nai[d] == LSEQ - 1) a = 0.f;
        e[d] = a;
        s += a;
    }

    #pragma unroll
    for (int i = 0; i < 7; i++) {
        int idx = lane + 32 * i;
        if (idx < FF) {
            float v = 0.f;
            #pragma unroll
            for (int d = 0; d < DD; d++) v += e[d] * nv[d][i];
            ctxpre[(size_t)r * FF + idx] = __float2half_rn(v);
        }
    }
    if (lane == 0) srow[r] = s;
}

// ---------------- GRU pointwise ---------------------------------------------
__global__ void gru_kernel(const float* __restrict__ gi, const float* __restrict__ gh,
                           const __half* __restrict__ cur,
                           __half* __restrict__ outh, float* __restrict__ outf,
                           int final_round)
{
    int idx = blockIdx.x * blockDim.x + threadIdx.x;
    if (idx >= MROWS * FF) return;
    int r = idx / FF;
    int j = idx - r * FF;
    size_t base = (size_t)r * 3 * FF + j;
    float ir = gi[base], iz = gi[base + FF], in_ = gi[base + 2 * FF];
    float hr = gh[base], hz = gh[base + FF], hn  = gh[base + 2 * FF];
    float rr = 1.f / (1.f + expf(-(ir + hr)));
    float z  = 1.f / (1.f + expf(-(iz + hz)));
    float n  = tanhf(in_ + rr * hn);
    float c  = __half2float(cur[idx]);
    float h  = (1.f - z) * n + z * c;
    h = (h > 0.f) ? h : 0.f;
    if (final_round) outf[idx] = h;
    else             outh[idx] = __float2half_rn(h);
}

// ---------------- launch ------------------------------------------------------
static inline int ceil_div(int a, int b) { return (a + b - 1) / b; }

extern "C" void kernel_launch(void* const* d_in, const int* in_sizes, int n_in,
                              void* d_out, int out_size)
{
    const float* atom_list = (const float*)d_in[0];
    const float* bond_list = (const float*)d_in[1];
    const int*   adeg      = (const int*)  d_in[2];
    const int*   bdeg      = (const int*)  d_in[3];
    const float* atom_W    = (const float*)d_in[4];
    const float* atom_b    = (const float*)d_in[5];
    const float* nbr_W     = (const float*)d_in[6];
    const float* nbr_b     = (const float*)d_in[7];
    const float* align_W   = (const float*)d_in[8];
    const float* align_b   = (const float*)d_in[9];
    const float* attend_W  = (const float*)d_in[10];
    const float* attend_b  = (const float*)d_in[11];
    const float* gWih      = (const float*)d_in[12];
    const float* gWhh      = (const float*)d_in[13];
    const float* gbih      = (const float*)d_in[14];
    const float* gbhh      = (const float*)d_in[15];
    float* out = (float*)d_out;

    __half *cur, *ctxpre, *ctx, *nbr, *acat, *atomh;
    __half *atomWh, *nbrWh, *attWh, *Wihh, *Whhh;
    float *s, *gi, *gh;
    cudaGetSymbolAddress((void**)&cur,    h_cur);
    cudaGetSymbolAddress((void**)&ctxpre, h_ctxpre);
    cudaGetSymbolAddress((void**)&ctx,    h_ctx);
    cudaGetSymbolAddress((void**)&s,      g_s);
    cudaGetSymbolAddress((void**)&gi,     g_gi);
    cudaGetSymbolAddress((void**)&gh,     g_gh);
    cudaGetSymbolAddress((void**)&nbr,    h_nbr);
    cudaGetSymbolAddress((void**)&acat,   h_acat);
    cudaGetSymbolAddress((void**)&atomh,  h_atom);
    cudaGetSymbolAddress((void**)&atomWh, h_atomW);
    cudaGetSymbolAddress((void**)&nbrWh,  h_nbrW);
    cudaGetSymbolAddress((void**)&attWh,  h_attW);
    cudaGetSymbolAddress((void**)&Wihh,   h_Wih);
    cudaGetSymbolAddress((void**)&Whhh,   h_Whh);

    // ---- fp16 (padded) copies of all GEMM operands ----
    w2h_pad<<<ceil_div(MROWS * KPA, 256), 256>>>(atom_list, atomh, MROWS, FA_, KPA);
    w2h_pad<<<ceil_div(FF * KPA, 256), 256>>>(atom_W, atomWh, FF, FA_, KPA);
    w2h_pad<<<ceil_div(FF * KPC, 256), 256>>>(nbr_W, nbrWh, FF, KC, KPC);
    w2h_pad<<<ceil_div(RR * FF * FF, 256), 256>>>(attend_W, attWh, RR * FF, FF, FF);
    w2h_pad<<<ceil_div(RR * 3 * FF * FF, 256), 256>>>(gWih, Wihh, RR * 3 * FF, FF, FF);
    w2h_pad<<<ceil_div(RR * 3 * FF * FF, 256), 256>>>(gWhh, Whhh, RR * 3 * FF, FF, FF);

    // 1. cur = leaky(atom_list @ atom_W^T + atom_b)   [32768 x 200, K=40]
    gemm_h<1, 1><<<dim3(ceil_div(FF, SBN), MROWS / SBM), 256>>>(
        atomh, atomWh, atom_b, nullptr, cur, MROWS, FF, KPA);

    // 2. gather concat inputs (half, padded)
    gather_acat_kernel<<<ceil_div(MSLOT * KPC, 256), 256>>>(
        atom_list, bond_list, adeg, bdeg, acat);

    // 3. nbrfeat = leaky(acat @ nbr_W^T + nbr_b)      [196608 x 200, K=56]
    gemm_h<1, 1><<<dim3(ceil_div(FF, SBN), MSLOT / SBM), 256>>>(
        acat, nbrWh, nbr_b, nullptr, nbr, MSLOT, FF, KPC);

    for (int d = 0; d < RR; d++) {
        attention_kernel<<<MROWS / 8, 256>>>(
            cur, nbr, adeg,
            align_W + (size_t)d * 2 * FF, align_b + d,
            ctxpre, s, (d == 0) ? 1 : 0);

        // context = elu(ctxpre @ attend_W^T + attend_b * s)  [32768 x 200, K=200]
        gemm_h<2, 1><<<dim3(ceil_div(FF, SBN), MROWS / SBM), 256>>>(
            ctxpre, attWh + (size_t)d * FF * FF, attend_b + (size_t)d * FF, s,
            ctx, MROWS, FF, KPF);

        // gi = context @ Wih^T + bih                  [32768 x 600, K=200]
        gemm_h<0, 0><<<dim3(ceil_div(3 * FF, SBN), MROWS / SBM), 256>>>(
            ctx, Wihh + (size_t)d * 3 * FF * FF, gbih + (size_t)d * 3 * FF, nullptr,
            gi, MROWS, 3 * FF, KPF);

        // gh = cur @ Whh^T + bhh
        gemm_h<0, 0><<<dim3(ceil_div(3 * FF, SBN), MROWS / SBM), 256>>>(
            cur, Whhh + (size_t)d * 3 * FF * FF, gbhh + (size_t)d * 3 * FF, nullptr,
            gh, MROWS, 3 * FF, KPF);

        gru_kernel<<<ceil_div(MROWS * FF, 256), 256>>>(
            gi, gh, cur, cur, out, (d == RR - 1) ? 1 : 0);
    }
}

// round 10
// speedup vs baseline: 1.4979x; 1.0082x over previous
#include <cuda_runtime.h>
#include <cuda_fp16.h>
#include <cstddef>

// Problem constants
#define BATCH 256
#define LSEQ  128
#define DD    6
#define FF    200
#define FA_   39
#define FB_   10
#define RR    2
#define MROWS (BATCH*LSEQ)          // 32768
#define MSLOT (MROWS*DD)            // 196608
#define KC    (FA_+FB_)             // 49
#define KPA   40                    // padded K for atom GEMM
#define KPC   56                    // padded K for nbr GEMM
#define KPF   200                   // F (16B-aligned rows: 400B)

// ---------------- scratch (device globals; no allocations allowed) ----------
__device__ __half h_cur   [(size_t)MROWS*FF];
__device__ __half h_cur2  [(size_t)MROWS*FF];
__device__ __half h_ctxpre[(size_t)MROWS*FF];
__device__ __half h_ctx   [(size_t)MROWS*FF];
__device__ float  g_s     [MROWS];
__device__ __half h_nbr   [(size_t)MSLOT*FF];
__device__ __half h_acat  [(size_t)MSLOT*KPC];
__device__ __half h_atom  [(size_t)MROWS*KPA];
__device__ __half h_atomW [FF*KPA];
__device__ __half h_nbrW  [FF*KPC];
__device__ __half h_attW  [RR*FF*FF];
__device__ __half h_Wih   [(size_t)RR*3*FF*FF];
__device__ __half h_Whh   [(size_t)RR*3*FF*FF];

// ---------------- PTX helpers ------------------------------------------------
__device__ __forceinline__ void mma_f16(float* c, const unsigned* a, const unsigned* b) {
    asm volatile(
        "mma.sync.aligned.m16n8k16.row.col.f32.f16.f16.f32 "
        "{%0,%1,%2,%3}, {%4,%5,%6,%7}, {%8,%9}, {%0,%1,%2,%3};"
        : "+f"(c[0]), "+f"(c[1]), "+f"(c[2]), "+f"(c[3])
        : "r"(a[0]), "r"(a[1]), "r"(a[2]), "r"(a[3]), "r"(b[0]), "r"(b[1]));
}

__device__ __forceinline__ void ldsm4(unsigned& r0, unsigned& r1, unsigned& r2, unsigned& r3,
                                      const void* p) {
    unsigned addr = (unsigned)__cvta_generic_to_shared(p);
    asm volatile("ldmatrix.sync.aligned.m8n8.x4.shared.b16 {%0,%1,%2,%3}, [%4];"
                 : "=r"(r0), "=r"(r1), "=r"(r2), "=r"(r3) : "r"(addr));
}

__device__ __forceinline__ void cpa16h(__half* dst, const __half* src, int bytes) {
    unsigned d = (unsigned)__cvta_generic_to_shared(dst);
    asm volatile("cp.async.cg.shared.global [%0], [%1], 16, %2;\n"
                 :: "r"(d), "l"(src), "r"(bytes));
}
__device__ __forceinline__ void cp_commit() { asm volatile("cp.async.commit_group;\n"); }
__device__ __forceinline__ void cp_wait_1() { asm volatile("cp.async.wait_group 1;\n"); }

// =================== fp16 tensor-core GEMM (cp.async + ldmatrix) ============
//   C[M,N] = act(A[M,Kp] @ W[N,Kp]^T + bias[N]*rowscale[M])
//   ACT: 0=none, 1=leaky_relu(0.01), 2=elu.  OUTH: 1 -> store __half.
#define SBM 128
#define SBN 128
#define NSTAGE 3

template<int ACT, int OUTH>
__global__ void __launch_bounds__(256, 2)
gemm_h(const __half* __restrict__ A, const __half* __restrict__ W,
       const float* __restrict__ bias, const float* __restrict__ rowscale,
       void* __restrict__ Cv, int M, int N, int Kp)
{
    __shared__ __align__(16) __half As[NSTAGE][SBM][16];
    __shared__ __align__(16) __half Bs[NSTAGE][SBN][16];

    const int tid   = threadIdx.x;
    const int lane  = tid & 31;
    const int warp  = tid >> 5;
    const int warpM = warp & 1;
    const int warpN = warp >> 1;
    const int mBase = blockIdx.y * SBM;
    const int nBase = blockIdx.x * SBN;
    const int nk    = (Kp + 15) / 16;
    const int r0 = lane >> 2;
    const int c0 = lane & 3;
    const int lrowA = ((lane >> 3) & 1) * 8 + (lane & 7);
    const int lchA  = lane >> 4;
    const int lrowB = (lane >> 4) * 8 + (lane & 7);
    const int lchB  = (lane >> 3) & 1;

    float acc[4][4][4];
    #pragma unroll
    for (int mt = 0; mt < 4; mt++)
        #pragma unroll
        for (int nt = 0; nt < 4; nt++)
            #pragma unroll
            for (int i = 0; i < 4; i++) acc[mt][nt][i] = 0.f;

#define LOAD(S, KT)                                                            \
    {                                                                          \
        int kbase = (KT) * 16;                                                 \
        {                                                                      \
            int m = tid >> 1, c = tid & 1;                                     \
            int k0 = kbase + c * 8;                                            \
            int bytes = (k0 < Kp) ? 16 : 0;                                    \
            const __half* src = A + (size_t)(mBase + m) * Kp + (bytes ? k0 : 0);\
            cpa16h(&As[S][m][(c ^ ((m >> 2) & 1)) * 8], src, bytes);           \
        }                                                                      \
        {                                                                      \
            int n = tid >> 1, c = tid & 1;                                     \
            int gn = nBase + n, k0 = kbase + c * 8;                            \
            int bytes = (gn < N && k0 < Kp) ? 16 : 0;                          \
            const __half* src = W + (size_t)(gn < N ? gn : 0) * Kp             \
                                  + (bytes ? k0 : 0);                          \
            cpa16h(&Bs[S][n][(c ^ ((n >> 2) & 1)) * 8], src, bytes);           \
        }                                                                      \
        cp_commit();                                                           \
    }

    #pragma unroll
    for (int s = 0; s < NSTAGE - 1; s++) {
        if (s < nk) { LOAD(s, s); } else { cp_commit(); }
    }

    for (int kt = 0; kt < nk; kt++) {
        const int st = kt % NSTAGE;
        cp_wait_1();
        __syncthreads();

        int ktn = kt + NSTAGE - 1;
        if (ktn < nk) { LOAD(ktn % NSTAGE, ktn); } else { cp_commit(); }

        const __half (*as)[16] = As[st];
        const __half (*bs)[16] = Bs[st];

        unsigned a[4][4];
        #pragma unroll
        for (int mt = 0; mt < 4; mt++) {
            int row = warpM * 64 + mt * 16 + lrowA;
            int swc = lchA ^ ((row >> 2) & 1);
            ldsm4(a[mt][0], a[mt][1], a[mt][2], a[mt][3], &as[row][swc * 8]);
        }
        unsigned b[4][2];
        #pragma unroll
        for (int p = 0; p < 2; p++) {
            int row = warpN * 32 + p * 16 + lrowB;
            int swc = lchB ^ ((row >> 2) & 1);
            unsigned t0, t1, t2, t3;
            ldsm4(t0, t1, t2, t3, &bs[row][swc * 8]);
            b[2 * p][0]     = t0; b[2 * p][1]     = t1;
            b[2 * p + 1][0] = t2; b[2 * p + 1][1] = t3;
        }
        #pragma unroll
        for (int mt = 0; mt < 4; mt++)
            #pragma unroll
            for (int nt = 0; nt < 4; nt++)
                mma_f16(acc[mt][nt], a[mt], b[nt]);
    }

    float*  Cf = (float*)Cv;
    __half* Ch = (__half*)Cv;
    #pragma unroll
    for (int mt = 0; mt < 4; mt++) {
        int row0 = mBase + warpM * 64 + mt * 16 + r0;
        float s0 = rowscale ? rowscale[row0]     : 1.f;
        float s1 = rowscale ? rowscale[row0 + 8] : 1.f;
        #pragma unroll
        for (int nt = 0; nt < 4; nt++) {
            int col0 = nBase + warpN * 32 + nt * 8 + c0 * 2;
            #pragma unroll
            for (int j = 0; j < 2; j++) {
                int col = col0 + j;
                if (col < N) {
                    float bv = bias[col];
                    float v0 = acc[mt][nt][j]     + bv * s0;
                    float v1 = acc[mt][nt][j + 2] + bv * s1;
                    if (ACT == 1) {
                        v0 = (v0 > 0.f) ? v0 : 0.01f * v0;
                        v1 = (v1 > 0.f) ? v1 : 0.01f * v1;
                    } else if (ACT == 2) {
                        v0 = (v0 > 0.f) ? v0 : expm1f(v0);
                        v1 = (v1 > 0.f) ? v1 : expm1f(v1);
                    }
                    if (OUTH) {
                        Ch[(size_t)row0 * N + col]       = __float2half_rn(v0);
                        Ch[(size_t)(row0 + 8) * N + col] = __float2half_rn(v1);
                    } else {
                        Cf[(size_t)row0 * N + col]       = v0;
                        Cf[(size_t)(row0 + 8) * N + col] = v1;
                    }
                }
            }
        }
    }
#undef LOAD
}

// =================== fused gi+gh GEMM + GRU epilogue =========================
// Block: 128 rows x 16 F-cols; computes 6 gate tiles (Ncat = 96) with K=200.
// Warps: 4 warpM (32 rows) x 2 warpN (warpN0: Wih gates w/ ctx A; warpN1: Whh
// gates w/ cur A). Epilogue: warpN1 dumps acc to smem (stride 49), warpN0
// computes GRU gates + relu and writes the new hidden state.
#define GBM 128
#define GNC 96

__global__ void __launch_bounds__(256, 2)
gru_fused(const __half* __restrict__ ctx, const __half* __restrict__ cur,
          const __half* __restrict__ Wih, const __half* __restrict__ Whh,
          const float* __restrict__ bih, const float* __restrict__ bhh,
          __half* __restrict__ curout, float* __restrict__ outf, int finalr)
{
    // pipeline: per stage 128(ctx)+128(cur)+96(B) rows x 16 halves = 11264 B
    __shared__ __align__(16) __half smraw[NSTAGE * (GBM + GBM + GNC) * 16];

    const int tid   = threadIdx.x;
    const int lane  = tid & 31;
    const int warp  = tid >> 5;
    const int warpM = warp & 3;         // 0..3 -> 32 rows
    const int warpN = warp >> 2;        // 0..1
    const int mBase = blockIdx.y * GBM;
    const int jBase = blockIdx.x * 16;
    const int nk    = (KPF + 15) / 16;  // 13
    const int r0 = lane >> 2;
    const int c0 = lane & 3;
    const int lrowA = ((lane >> 3) & 1) * 8 + (lane & 7);
    const int lchA  = lane >> 4;
    const int lrowB = (lane >> 4) * 8 + (lane & 7);
    const int lchB  = (lane >> 3) & 1;

    float acc[2][6][4];
    #pragma unroll
    for (int mt = 0; mt < 2; mt++)
        #pragma unroll
        for (int nt = 0; nt < 6; nt++)
            #pragma unroll
            for (int i = 0; i < 4; i++) acc[mt][nt][i] = 0.f;

#define STG_CTX(S) ((__half(*)[16])(smraw + (size_t)(S) * (GBM+GBM+GNC) * 16))
#define STG_CUR(S) ((__half(*)[16])(smraw + ((size_t)(S) * (GBM+GBM+GNC) + GBM) * 16))
#define STG_B(S)   ((__half(*)[16])(smraw + ((size_t)(S) * (GBM+GBM+GNC) + 2*GBM) * 16))

#define FLOAD(S, KT)                                                           \
    {                                                                          \
        int kbase = (KT) * 16;                                                 \
        {                                                                      \
            int m = tid >> 1, c = tid & 1;                                     \
            int k0 = kbase + c * 8;                                            \
            int bytes = (k0 < KPF) ? 16 : 0;                                   \
            size_t off = (size_t)(mBase + m) * KPF + (bytes ? k0 : 0);         \
            int sc = (c ^ ((m >> 2) & 1)) * 8;                                 \
            cpa16h(&STG_CTX(S)[m][sc], ctx + off, bytes);                      \
            cpa16h(&STG_CUR(S)[m][sc], cur + off, bytes);                      \
        }                                                                      \
        if (tid < 2 * GNC) {                                                   \
            int rn = tid >> 1, c = tid & 1;                                    \
            int gate = rn >> 4;                                                \
            int jj = jBase + (rn & 15);                                        \
            int k0 = kbase + c * 8;                                            \
            int bytes = (jj < FF && k0 < KPF) ? 16 : 0;                        \
            int jjc = (jj < FF) ? jj : 0;                                      \
            const __half* src = (gate < 3)                                     \
                ? Wih + ((size_t)gate * FF + jjc) * KPF                        \
                : Whh + ((size_t)(gate - 3) * FF + jjc) * KPF;                 \
            cpa16h(&STG_B(S)[rn][(c ^ ((rn >> 2) & 1)) * 8],                   \
                   src + (bytes ? k0 : 0), bytes);                             \
        }                                                                      \
        cp_commit();                                                           \
    }

    #pragma unroll
    for (int s = 0; s < NSTAGE - 1; s++) { FLOAD(s, s); }

    for (int kt = 0; kt < nk; kt++) {
        const int st = kt % NSTAGE;
        cp_wait_1();
        __syncthreads();

        int ktn = kt + NSTAGE - 1;
        if (ktn < nk) { FLOAD(ktn % NSTAGE, ktn); } else { cp_commit(); }

        const __half (*amat)[16] = warpN ? STG_CUR(st) : STG_CTX(st);
        const __half (*bs)[16]   = STG_B(st);

        unsigned a[2][4];
        #pragma unroll
        for (int mt = 0; mt < 2; mt++) {
            int row = warpM * 32 + mt * 16 + lrowA;
            int swc = lchA ^ ((row >> 2) & 1);
            ldsm4(a[mt][0], a[mt][1], a[mt][2], a[mt][3], &amat[row][swc * 8]);
        }
        unsigned b[6][2];
        #pragma unroll
        for (int p = 0; p < 3; p++) {
            int row = warpN * 48 + p * 16 + lrowB;
            int swc = lchB ^ ((row >> 2) & 1);
            unsigned t0, t1, t2, t3;
            ldsm4(t0, t1, t2, t3, &bs[row][swc * 8]);
            b[2 * p][0]     = t0; b[2 * p][1]     = t1;
            b[2 * p + 1][0] = t2; b[2 * p + 1][1] = t3;
        }
        #pragma unroll
        for (int mt = 0; mt < 2; mt++)
            #pragma unroll
            for (int nt = 0; nt < 6; nt++)
                mma_f16(acc[mt][nt], a[mt], b[nt]);
    }

    // -------- exchange + GRU epilogue --------
    __syncthreads();                    // all reads of pipeline smem done
    float* ex = (float*)smraw;          // [4*32][49] padded: 25088 B <= 33792 B
    if (warpN == 1) {
        int base = (warpM * 32 + lane) * 49;
        #pragma unroll
        for (int mt = 0; mt < 2; mt++)
            #pragma unroll
            for (int nt = 0; nt < 6; nt++)
                #pragma unroll
                for (int i = 0; i < 4; i++)
                    ex[base + mt * 24 + nt * 4 + i] = acc[mt][nt][i];
    }
    __syncthreads();
    if (warpN == 0) {
        int base = (warpM * 32 + lane) * 49;
        #pragma unroll
        for (int mt = 0; mt < 2; mt++) {
            #pragma unroll
            for (int jh = 0; jh < 2; jh++) {
                #pragma unroll
                for (int i = 0; i < 4; i++) {
                    int row = mBase + warpM * 32 + mt * 16 + r0 + ((i >> 1) ? 8 : 0);
                    int j   = jBase + jh * 8 + c0 * 2 + (i & 1);
                    if (j < FF) {
                        float ir  = acc[mt][0 + jh][i] + bih[j];
                        float iz  = acc[mt][2 + jh][i] + bih[FF + j];
                        float inn = acc[mt][4 + jh][i] + bih[2 * FF + j];
                        float hr  = ex[base + mt * 24 + (0 + jh) * 4 + i] + bhh[j];
                        float hz  = ex[base + mt * 24 + (2 + jh) * 4 + i] + bhh[FF + j];
                        float hn  = ex[base + mt * 24 + (4 + jh) * 4 + i] + bhh[2 * FF + j];
                        float r = 1.f / (1.f + expf(-(ir + hr)));
                        float z = 1.f / (1.f + expf(-(iz + hz)));
                        float n = tanhf(inn + r * hn);
                        float c = __half2float(cur[(size_t)row * FF + j]);
                        float h = (1.f - z) * n + z * c;
                        h = (h > 0.f) ? h : 0.f;
                        if (finalr) outf[(size_t)row * FF + j] = h;
                        else        curout[(size_t)row * FF + j] = __float2half_rn(h);
                    }
                }
            }
        }
    }
#undef FLOAD
#undef STG_CTX
#undef STG_CUR
#undef STG_B
}

// ---------------- fp32 -> padded fp16 copy -----------------------------------
__global__ void w2h_pad(const float* __restrict__ in, __half* __restrict__ out,
                        int N, int K, int Kp)
{
    int i = blockIdx.x * blockDim.x + threadIdx.x;
    if (i >= N * Kp) return;
    int n = i / Kp, k = i - n * Kp;
    out[i] = (k < K) ? __float2half_rn(in[(size_t)n * K + k]) : __half(0.f);
}

// ---------------- gather concat(atom_nbr, bond_nbr) -> half [MSLOT, KPC] ----
__global__ void gather_acat_kernel(const float* __restrict__ atom_list,
                                   const float* __restrict__ bond_list,
                                   const int*   __restrict__ adeg,
                                   const int*   __restrict__ bdeg,
                                   __half* __restrict__ acat)
{
    int e = blockIdx.x * blockDim.x + threadIdx.x;
    if (e >= MSLOT * KPC) return;
    int slot = e / KPC;
    int k    = e - slot * KPC;
    int b    = slot / (LSEQ * DD);
    float v = 0.f;
    if (k < FA_) {
        int a = adeg[slot];
        v = atom_list[((size_t)b * LSEQ + a) * FA_ + k];
    } else if (k < KC) {
        int bb = bdeg[slot];
        v = bond_list[((size_t)b * LSEQ + bb) * FB_ + (k - FA_)];
    }
    acat[e] = __float2half_rn(v);
}

// ---------------- attention: warp per row ------------------------------------
__global__ void __launch_bounds__(256)
attention_kernel(const __half* __restrict__ cur,
                 const __half* __restrict__ nbrfeat,
                 const int*    __restrict__ adeg,
                 const float*  __restrict__ alignW,
                 const float*  __restrict__ alignB,
                 __half* __restrict__ ctxpre,
                 float*  __restrict__ srow,
                 int first)
{
    int gw   = (blockIdx.x * blockDim.x + threadIdx.x) >> 5;
    int lane = threadIdx.x & 31;
    if (gw >= MROWS) return;
    const int r = gw;
    const int b = r >> 7;
    const float ab = alignB[0];

    float cv[7], a0[7], a1[7];
    #pragma unroll
    for (int i = 0; i < 7; i++) {
        int idx = lane + 32 * i;
        bool ok = idx < FF;
        cv[i] = ok ? __half2float(cur[(size_t)r * FF + idx]) : 0.f;
        a0[i] = ok ? alignW[idx]      : 0.f;
        a1[i] = ok ? alignW[FF + idx] : 0.f;
    }
    float qd = 0.f;
    #pragma unroll
    for (int i = 0; i < 7; i++) qd += cv[i] * a0[i];
    #pragma unroll
    for (int o = 16; o > 0; o >>= 1) qd += __shfl_xor_sync(0xffffffffu, qd, o);

    float nv[DD][7];
    float score[DD];
    int   nai[DD];

    #pragma unroll
    for (int d = 0; d < DD; d++) {
        int na = adeg[r * DD + d];
        nai[d] = na;
        const __half* np = first ? (nbrfeat + ((size_t)r * DD + d) * FF)
                                 : (cur + ((size_t)(b * LSEQ + na)) * FF);
        float nd = 0.f;
        #pragma unroll
        for (int i = 0; i < 7; i++) {
            int idx = lane + 32 * i;
            float v = (idx < FF) ? __half2float(np[idx]) : 0.f;
            nv[d][i] = v;
            nd += v * a1[i];
        }
        #pragma unroll
        for (int o = 16; o > 0; o >>= 1) nd += __shfl_xor_sync(0xffffffffu, nd, o);
        float sc = qd + nd + ab;
        sc = (sc > 0.f) ? sc : 0.01f * sc;
        if (na == LSEQ - 1) sc = sc - 9e8f;
        score[d] = sc;
    }

    float mx = score[0];
    #pragma unroll
    for (int d = 1; d < DD; d++) mx = fmaxf(mx, score[d]);
    float e[DD], den = 0.f;
    #pragma unroll
    for (int d = 0; d < DD; d++) { e[d] = expf(score[d] - mx); den += e[d]; }
    float inv = 1.f / den;
    float s = 0.f;
    #pragma unroll
    for (int d = 0; d < DD; d++) {
        float a = e[d] * inv;
        if (nai[d] == LSEQ - 1) a = 0.f;
        e[d] = a;
        s += a;
    }

    #pragma unroll
    for (int i = 0; i < 7; i++) {
        int idx = lane + 32 * i;
        if (idx < FF) {
            float v = 0.f;
            #pragma unroll
            for (int d = 0; d < DD; d++) v += e[d] * nv[d][i];
            ctxpre[(size_t)r * FF + idx] = __float2half_rn(v);
        }
    }
    if (lane == 0) srow[r] = s;
}

// ---------------- launch ------------------------------------------------------
static inline int ceil_div(int a, int b) { return (a + b - 1) / b; }

extern "C" void kernel_launch(void* const* d_in, const int* in_sizes, int n_in,
                              void* d_out, int out_size)
{
    const float* atom_list = (const float*)d_in[0];
    const float* bond_list = (const float*)d_in[1];
    const int*   adeg      = (const int*)  d_in[2];
    const int*   bdeg      = (const int*)  d_in[3];
    const float* atom_W    = (const float*)d_in[4];
    const float* atom_b    = (const float*)d_in[5];
    const float* nbr_W     = (const float*)d_in[6];
    const float* nbr_b     = (const float*)d_in[7];
    const float* align_W   = (const float*)d_in[8];
    const float* align_b   = (const float*)d_in[9];
    const float* attend_W  = (const float*)d_in[10];
    const float* attend_b  = (const float*)d_in[11];
    const float* gWih      = (const float*)d_in[12];
    const float* gWhh      = (const float*)d_in[13];
    const float* gbih      = (const float*)d_in[14];
    const float* gbhh      = (const float*)d_in[15];
    float* out = (float*)d_out;

    __half *cur, *cur2, *ctxpre, *ctx, *nbr, *acat, *atomh;
    __half *atomWh, *nbrWh, *attWh, *Wihh, *Whhh;
    float *s;
    cudaGetSymbolAddress((void**)&cur,    h_cur);
    cudaGetSymbolAddress((void**)&cur2,   h_cur2);
    cudaGetSymbolAddress((void**)&ctxpre, h_ctxpre);
    cudaGetSymbolAddress((void**)&ctx,    h_ctx);
    cudaGetSymbolAddress((void**)&s,      g_s);
    cudaGetSymbolAddress((void**)&nbr,    h_nbr);
    cudaGetSymbolAddress((void**)&acat,   h_acat);
    cudaGetSymbolAddress((void**)&atomh,  h_atom);
    cudaGetSymbolAddress((void**)&atomWh, h_atomW);
    cudaGetSymbolAddress((void**)&nbrWh,  h_nbrW);
    cudaGetSymbolAddress((void**)&attWh,  h_attW);
    cudaGetSymbolAddress((void**)&Wihh,   h_Wih);
    cudaGetSymbolAddress((void**)&Whhh,   h_Whh);

    // ---- fp16 (padded) copies of all GEMM operands ----
    w2h_pad<<<ceil_div(MROWS * KPA, 256), 256>>>(atom_list, atomh, MROWS, FA_, KPA);
    w2h_pad<<<ceil_div(FF * KPA, 256), 256>>>(atom_W, atomWh, FF, FA_, KPA);
    w2h_pad<<<ceil_div(FF * KPC, 256), 256>>>(nbr_W, nbrWh, FF, KC, KPC);
    w2h_pad<<<ceil_div(RR * FF * FF, 256), 256>>>(attend_W, attWh, RR * FF, FF, FF);
    w2h_pad<<<ceil_div(RR * 3 * FF * FF, 256), 256>>>(gWih, Wihh, RR * 3 * FF, FF, FF);
    w2h_pad<<<ceil_div(RR * 3 * FF * FF, 256), 256>>>(gWhh, Whhh, RR * 3 * FF, FF, FF);

    // 1. cur = leaky(atom_list @ atom_W^T + atom_b)   [32768 x 200, K=40]
    gemm_h<1, 1><<<dim3(ceil_div(FF, SBN), MROWS / SBM), 256>>>(
        atomh, atomWh, atom_b, nullptr, cur, MROWS, FF, KPA);

    // 2. gather concat inputs (half, padded)
    gather_acat_kernel<<<ceil_div(MSLOT * KPC, 256), 256>>>(
        atom_list, bond_list, adeg, bdeg, acat);

    // 3. nbrfeat = leaky(acat @ nbr_W^T + nbr_b)      [196608 x 200, K=56]
    gemm_h<1, 1><<<dim3(ceil_div(FF, SBN), MSLOT / SBM), 256>>>(
        acat, nbrWh, nbr_b, nullptr, nbr, MSLOT, FF, KPC);

    __half* curbuf[2] = { cur, cur2 };
    for (int d = 0; d < RR; d++) {
        __half* curin  = curbuf[d & 1];
        __half* curoutp = curbuf[(d + 1) & 1];

        attention_kernel<<<MROWS / 8, 256>>>(
            curin, nbr, adeg,
            align_W + (size_t)d * 2 * FF, align_b + d,
            ctxpre, s, (d == 0) ? 1 : 0);

        // context = elu(ctxpre @ attend_W^T + attend_b * s)  [32768 x 200, K=200]
        gemm_h<2, 1><<<dim3(ceil_div(FF, SBN), MROWS / SBM), 256>>>(
            ctxpre, attWh + (size_t)d * FF * FF, attend_b + (size_t)d * FF, s,
            ctx, MROWS, FF, KPF);

        // fused gi+gh GEMM + GRU: writes new hidden (or fp32 out on final round)
        gru_fused<<<dim3(13, MROWS / GBM), 256>>>(
            ctx, curin,
            Wihh + (size_t)d * 3 * FF * FF, Whhh + (size_t)d * 3 * FF * FF,
            gbih + (size_t)d * 3 * FF, gbhh + (size_t)d * 3 * FF,
            curoutp, out, (d == RR - 1) ? 1 : 0);
    }
}